// round 17
// baseline (speedup 1.0000x reference)
#include <cuda_runtime.h>
#include <cstdint>

// Problem shape constants (fixed by setup_inputs)
#define B_ 32
#define M_ 512
#define L_ 128
#define N_ 64
#define T_ 40
#define A_ 6
#define Z_ 64
#define C_ 3

#define WARPS_PER_BLOCK 16      // 512-thread blocks -> 2560 blocks total
#define TP_ (T_ / 2)            // t-pairs per (b,n) = 20

// ---------------------------------------------------------------------------
// Algebraic fact (validated since R13, rel_err 1.05e-7): the frenet projection
// term is uniform across actions and cancels exactly under the reference's
// feasibility-masked mean subtraction. So
//   logits[a] = <df[a,:], z> + (ctx[a,:]·w − masked_mean_a(ctx·w))
// and the polyline projection pipeline is dead code.
//
// R17: kernel body is R15's validated 2-t-per-warp layout (28.0us kernel, the
// measured DRAM floor ~4.95 TB/s). Changes target the only two variables that
// moved across R13/R15/R16:
//   (1) 512-thread blocks -> 2560 blocks. Measured per-block overhead outside
//       kernel exec ~0.26ns/block (2.7us @10240 blocks vs 0.3us @2048).
//   (2) __ldcs (evict-first) on the touch-once streams df/ctx/fa so they
//       don't displace the reused z rows in L2.
//
// Lane layout: halves h=0/1 own even/odd actions; z as float4 over 16 lanes
// (replicated per half). acc[p] p=0..2 -> t0 actions 2p+h, p=3..5 -> t1.
// 6 back-to-back coalesced 512B LDG.128 span 3072 contiguous df bytes.
// ---------------------------------------------------------------------------
__global__ __launch_bounds__(32 * WARPS_PER_BLOCK)
void logits_kernel(const float* __restrict__ df,
                   const float* __restrict__ ctx,
                   const int* __restrict__ fa,
                   const float* __restrict__ z,
                   const float* __restrict__ w,
                   float* __restrict__ out) {
    const int gwp  = (blockIdx.x * blockDim.x + threadIdx.x) >> 5;  // warp id
    const int lane = threadIdx.x & 31;
    if (gwp >= B_ * N_ * TP_) return;
    const int bn  = gwp / TP_;
    const int gw0 = bn * T_ + 2 * (gwp % TP_);   // first of two consecutive t's

    const int h = lane >> 4;      // half: 0 -> even actions, 1 -> odd actions
    const int q = lane & 15;

    // z as float4 per lane, replicated across halves (kept cacheable: reused
    // by all 20 warps of this bn)
    const float4 z4 = *reinterpret_cast<const float4*>(z + (size_t)bn * Z_ + 4 * q);

    // 6 coalesced 512B streaming loads covering df rows for t0 and t1.
    // p = 0..2 -> t0 action-pairs, p = 3..5 -> t1 action-pairs.
    const float4* dfb =
        reinterpret_cast<const float4*>(df + (size_t)gw0 * (A_ * Z_) + 4 * lane);
    float4 v[6];
#pragma unroll
    for (int p = 0; p < 6; ++p)
        v[p] = __ldcs(dfb + p * (2 * Z_ / 4));

    // ctx: 36 contiguous floats (18 per t); fa: 12 contiguous ints (streamed)
    const size_t cb = (size_t)gw0 * (A_ * C_);
    const float cv0 = (lane < A_ * C_) ? __ldcs(ctx + cb + lane) : 0.f;
    const float cv1 = (lane < A_ * C_) ? __ldcs(ctx + cb + A_ * C_ + lane) : 0.f;
    const int f = (lane < 2 * A_) ? __ldcs(fa + (size_t)gw0 * A_ + lane) : 0;

    float acc[6];
#pragma unroll
    for (int p = 0; p < 6; ++p)
        acc[p] = v[p].x * z4.x + v[p].y * z4.y + v[p].z * z4.z + v[p].w * z4.w;

    // 4-level butterfly within each 16-lane half:
    // afterwards every lane in half h holds the full dot for its action
#pragma unroll
    for (int p = 0; p < 6; ++p) {
#pragma unroll
        for (int off = 8; off > 0; off >>= 1)
            acc[p] += __shfl_xor_sync(0xffffffffu, acc[p], off);
    }

    // ctx·w per action for both t's: segmented 3-sums, valid at lanes 3a
    const float w0 = __ldg(w), w1 = __ldg(w + 1), w2 = __ldg(w + 2);
    const int   c  = lane % 3;
    const float wc = (c == 0) ? w0 : ((c == 1) ? w1 : w2);
    const float pt0 = cv0 * wc;
    const float pt1 = cv1 * wc;
    const float qs0 = pt0 + __shfl_down_sync(0xffffffffu, pt0, 1)
                          + __shfl_down_sync(0xffffffffu, pt0, 2);
    const float qs1 = pt1 + __shfl_down_sync(0xffffffffu, pt1, 1)
                          + __shfl_down_sync(0xffffffffu, pt1, 2);
    float ua0[3], ua1[3];
#pragma unroll
    for (int r = 0; r < 3; ++r) {
        const int src = 3 * (2 * r + h);
        ua0[r] = __shfl_sync(0xffffffffu, qs0, src);
        ua1[r] = __shfl_sync(0xffffffffu, qs1, src);
    }

    // One ballot serves both t's: lanes 0..5 -> t0 mask, lanes 6..11 -> t1
    const unsigned bal = __ballot_sync(0xffffffffu, (f != 0) && (lane < 2 * A_));
    unsigned em0 = bal & 0x3fu;         if (!em0) em0 = 0x3fu;
    unsigned em1 = (bal >> A_) & 0x3fu; if (!em1) em1 = 0x3fu;
    const int cnt0 = __popc(em0), cnt1 = __popc(em1);

    float part0 = 0.f, part1 = 0.f;
#pragma unroll
    for (int r = 0; r < 3; ++r) {
        const int a = 2 * r + h;
        part0 += ((em0 >> a) & 1u) ? ua0[r] : 0.f;
        part1 += ((em1 >> a) & 1u) ? ua1[r] : 0.f;
    }
    // each half's part is uniform across its lanes; cross-half add = total
    const float tot0  = part0 + __shfl_xor_sync(0xffffffffu, part0, 16);
    const float tot1  = part1 + __shfl_xor_sync(0xffffffffu, part1, 16);
    const float mean0 = tot0 / fmaxf((float)cnt0, 1e-6f);
    const float mean1 = tot1 / fmaxf((float)cnt1, 1e-6f);

    // lanes 0 and 16 write even/odd actions for both t's (12 contiguous floats)
    if (q == 0) {
        float* ob = out + (size_t)gw0 * A_ + h;
#pragma unroll
        for (int r = 0; r < 3; ++r) {
            ob[2 * r]      = acc[r]     + (ua0[r] - mean0);
            ob[A_ + 2 * r] = acc[3 + r] + (ua1[r] - mean1);
        }
    }
}

// ---------------------------------------------------------------------------
// kernel_launch: inputs in metadata order:
//   0 map_polylines (B,M,L,2) f32   1 idx (B,N) i32       2 pts (B,N,2) f32
//   3 z (B,N,Z) f32                 4 decision_features (B,N,T,A,Z) f32
//   5 ctx_features (B,N,T,A,C) f32  6 feasible_actions (B,N,T,A) i32
//   7 u_ctx_w (C,) f32              8 u_ctx_b (1,) f32
// output: logits (B,N,T,A) f32
// Inputs 0,1,2,8 provably do not affect the output (constant term cancels
// under the masked mean).
// ---------------------------------------------------------------------------
extern "C" void kernel_launch(void* const* d_in, const int* in_sizes, int n_in,
                              void* d_out, int out_size) {
    const float* z    = (const float*)d_in[3];
    const float* df   = (const float*)d_in[4];
    const float* ctx  = (const float*)d_in[5];
    const int*   fa   = (const int*)  d_in[6];
    const float* w    = (const float*)d_in[7];
    float* out = (float*)d_out;

    // 40960 pair-warps, 16 warps/block -> 2560 blocks
    logits_kernel<<<(B_ * N_ * TP_) / WARPS_PER_BLOCK, 32 * WARPS_PER_BLOCK>>>(
        df, ctx, fa, z, w, out);
}